// round 13
// baseline (speedup 1.0000x reference)
#include <cuda_runtime.h>
#include <cstdint>
#include <math.h>

// ---------------- problem constants ----------------
#define B_ROWS   8192
#define EXP_DIM  1024
#define DICT     4096
#define N_ITERS  20
#define STEP_SZ  0.1f
#define THRESH   0.01f   // REG * STEP
#define K_SPARSE 409

// ---------------- tiling ----------------
#define TM 256
#define TN 128
#define TK 16
#define ALD 256          // A smem leading dim (floats)
#define BDLD 256         // B smem leading dim (floats, DUPLICATED pairs)
#define NTHREADS 256
#define SMEM_BYTES ((2 * TK * ALD + 2 * TK * BDLD) * 4)   // 65536

// scratch: residual [8192 x 1024] fp32 (allocation-free device global)
__device__ float g_resid[(size_t)B_ROWS * EXP_DIM];

// ---------------- f32x2 packed helpers (Blackwell FFMA2) ----------------
typedef unsigned long long u64;

__device__ __forceinline__ u64 pack2(float lo, float hi) {
    u64 r;
    asm("mov.b64 %0, {%1, %2};" : "=l"(r) : "f"(lo), "f"(hi));
    return r;
}
__device__ __forceinline__ void unpack2(u64 v, float& lo, float& hi) {
    asm("mov.b64 {%0, %1}, %2;" : "=f"(lo), "=f"(hi) : "l"(v));
}
__device__ __forceinline__ void fma2(u64& d, u64 a, u64 b) {
    asm("fma.rn.f32x2 %0, %1, %2, %0;" : "+l"(d) : "l"(a), "l"(b));
}

// ---------------- compute core: 16 k-steps, pure LDS.128 + FMA2 ----------------
// Thread tile 16(M) x 8(N). acc[p][j]: rows ty*16 + {2p,2p+1}, col tx*8 + j.
// A fragment: native u64 M-pairs.  B fragment: pre-duplicated u64 pairs.
__device__ __forceinline__ void compute_tile(const float (*As)[ALD],
                                             const float (*Bsd)[BDLD],
                                             u64 acc[8][8], int tx, int ty)
{
#pragma unroll
    for (int k = 0; k < TK; k++) {
        const ulonglong2* pA = reinterpret_cast<const ulonglong2*>(&As[k][ty * 16]);
        ulonglong2 a0 = pA[0], a1 = pA[1], a2 = pA[2], a3 = pA[3];
        u64 ap[8] = {a0.x, a0.y, a1.x, a1.y, a2.x, a2.y, a3.x, a3.y};

        const ulonglong2* pB = reinterpret_cast<const ulonglong2*>(&Bsd[k][tx * 16]);
        ulonglong2 b0 = pB[0], b1 = pB[1], b2 = pB[2], b3 = pB[3];
        u64 bd[8] = {b0.x, b0.y, b1.x, b1.y, b2.x, b2.y, b3.x, b3.y};

#pragma unroll
        for (int p = 0; p < 8; p++)
#pragma unroll
            for (int j = 0; j < 8; j++) fma2(acc[p][j], ap[p], bd[j]);
    }
}

// ---------------------------------------------------------------------------
// GEMM1: resid[8192,1024] = X - alpha[8192,4096] @ D[4096,1024]   (NN)
// ---------------------------------------------------------------------------
__global__ __launch_bounds__(NTHREADS, 1)
void gemm1_kernel(const float* __restrict__ alpha,
                  const float* __restrict__ Dmat,
                  const float* __restrict__ X)
{
    extern __shared__ float smem[];
    float (*As)[TK][ALD]  = reinterpret_cast<float (*)[TK][ALD]>(smem);
    float (*Bsd)[TK][BDLD] = reinterpret_cast<float (*)[TK][BDLD]>(smem + 2 * TK * ALD);

    const int tid = threadIdx.x;
    const int tx = tid & 15, ty = tid >> 4;
    const int m0 = blockIdx.y * TM, n0 = blockIdx.x * TN;

    const int arow = tid >> 2;      // 0..63  (+r*64) A row
    const int akq  = tid & 3;       // 0..3   A k-quad
    const int bkk  = tid >> 5;      // 0..7   (+r*8) B k row
    const int bnq  = tid & 31;      // 0..31  B n-quad

    u64 acc[8][8];
#pragma unroll
    for (int p = 0; p < 8; p++)
#pragma unroll
        for (int j = 0; j < 8; j++) acc[p][j] = 0ull;

    float4 pa[4], pb[2];

#define G1_LDG(kt) do {                                                           \
    _Pragma("unroll")                                                             \
    for (int r = 0; r < 4; r++)                                                   \
        pa[r] = *reinterpret_cast<const float4*>(                                 \
            alpha + (size_t)(m0 + arow + r * 64) * DICT + (kt) + akq * 4);        \
    _Pragma("unroll")                                                             \
    for (int r = 0; r < 2; r++)                                                   \
        pb[r] = *reinterpret_cast<const float4*>(                                 \
            Dmat + (size_t)((kt) + bkk + r * 8) * EXP_DIM + n0 + bnq * 4);        \
    } while (0)

#define G1_STS(buf) do {                                                          \
    _Pragma("unroll")                                                             \
    for (int r = 0; r < 4; r++) {                                                 \
        int mm = arow + r * 64;                                                   \
        As[buf][akq * 4 + 0][mm] = pa[r].x;                                       \
        As[buf][akq * 4 + 1][mm] = pa[r].y;                                       \
        As[buf][akq * 4 + 2][mm] = pa[r].z;                                       \
        As[buf][akq * 4 + 3][mm] = pa[r].w;                                       \
    }                                                                             \
    _Pragma("unroll")                                                             \
    for (int r = 0; r < 2; r++) {                                                 \
        int kk = bkk + r * 8;                                                     \
        ulonglong2* dst = reinterpret_cast<ulonglong2*>(&Bsd[buf][kk][bnq * 8]);  \
        dst[0] = make_ulonglong2(pack2(pb[r].x, pb[r].x), pack2(pb[r].y, pb[r].y)); \
        dst[1] = make_ulonglong2(pack2(pb[r].z, pb[r].z), pack2(pb[r].w, pb[r].w)); \
    } } while (0)

    G1_LDG(0);
    G1_STS(0);
    __syncthreads();

    const int nT = DICT / TK;
    for (int kt = 0; kt < nT; kt++) {
        const int buf = kt & 1;
        if (kt + 1 < nT) G1_LDG((kt + 1) * TK);
        compute_tile(As[buf], Bsd[buf], acc, tx, ty);
        if (kt + 1 < nT) {
            G1_STS(1 - buf);
            __syncthreads();
        }
    }
#undef G1_LDG
#undef G1_STS

    // epilogue: resid = X - acc
#pragma unroll
    for (int p = 0; p < 8; p++) {
        float lo[8], hi[8];
#pragma unroll
        for (int j = 0; j < 8; j++) unpack2(acc[p][j], lo[j], hi[j]);
        const int r0 = m0 + ty * 16 + 2 * p;
        const int col = n0 + tx * 8;
#pragma unroll
        for (int h = 0; h < 2; h++) {
            const int row = r0 + h;
            const float* vals = h ? hi : lo;
            const float* xptr = X + (size_t)row * EXP_DIM + col;
            float* optr = &g_resid[(size_t)row * EXP_DIM + col];
#pragma unroll
            for (int j = 0; j < 8; j += 4) {
                float4 xv = *reinterpret_cast<const float4*>(xptr + j);
                float4 o = make_float4(xv.x - vals[j], xv.y - vals[j + 1],
                                       xv.z - vals[j + 2], xv.w - vals[j + 3]);
                *reinterpret_cast<float4*>(optr + j) = o;
            }
        }
    }
}

// ---------------------------------------------------------------------------
// GEMM2: alpha = shrink(alpha + STEP * resid[8192,1024] @ D^T)    (NT)
// ---------------------------------------------------------------------------
template <bool FIRST>
__global__ __launch_bounds__(NTHREADS, 1)
void gemm2_kernel(const float* __restrict__ Dmat,
                  float* __restrict__ alpha)
{
    extern __shared__ float smem[];
    float (*As)[TK][ALD]  = reinterpret_cast<float (*)[TK][ALD]>(smem);
    float (*Bsd)[TK][BDLD] = reinterpret_cast<float (*)[TK][BDLD]>(smem + 2 * TK * ALD);

    const int tid = threadIdx.x;
    const int tx = tid & 15, ty = tid >> 4;
    const int m0 = blockIdx.y * TM, n0 = blockIdx.x * TN;

    const int arow = tid >> 2;      // 0..63 (+r*64)
    const int akq  = tid & 3;       // 0..3

    u64 acc[8][8];
#pragma unroll
    for (int p = 0; p < 8; p++)
#pragma unroll
        for (int j = 0; j < 8; j++) acc[p][j] = 0ull;

    float4 pa[4], pb[2];

#define G2_LDG(kt) do {                                                           \
    _Pragma("unroll")                                                             \
    for (int r = 0; r < 4; r++)                                                   \
        pa[r] = *reinterpret_cast<const float4*>(                                 \
            &g_resid[(size_t)(m0 + arow + r * 64) * EXP_DIM + (kt) + akq * 4]);   \
    _Pragma("unroll")                                                             \
    for (int r = 0; r < 2; r++)                                                   \
        pb[r] = *reinterpret_cast<const float4*>(                                 \
            Dmat + (size_t)(n0 + arow + r * 64) * EXP_DIM + (kt) + akq * 4);      \
    } while (0)

#define G2_STS(buf) do {                                                          \
    _Pragma("unroll")                                                             \
    for (int r = 0; r < 4; r++) {                                                 \
        int mm = arow + r * 64;                                                   \
        As[buf][akq * 4 + 0][mm] = pa[r].x;                                       \
        As[buf][akq * 4 + 1][mm] = pa[r].y;                                       \
        As[buf][akq * 4 + 2][mm] = pa[r].z;                                       \
        As[buf][akq * 4 + 3][mm] = pa[r].w;                                       \
    }                                                                             \
    _Pragma("unroll")                                                             \
    for (int r = 0; r < 2; r++) {                                                 \
        int nn = arow + r * 64;                                                   \
        *reinterpret_cast<u64*>(&Bsd[buf][akq * 4 + 0][nn * 2]) = pack2(pb[r].x, pb[r].x); \
        *reinterpret_cast<u64*>(&Bsd[buf][akq * 4 + 1][nn * 2]) = pack2(pb[r].y, pb[r].y); \
        *reinterpret_cast<u64*>(&Bsd[buf][akq * 4 + 2][nn * 2]) = pack2(pb[r].z, pb[r].z); \
        *reinterpret_cast<u64*>(&Bsd[buf][akq * 4 + 3][nn * 2]) = pack2(pb[r].w, pb[r].w); \
    } } while (0)

    G2_LDG(0);
    G2_STS(0);
    __syncthreads();

    const int nT = EXP_DIM / TK;
    for (int kt = 0; kt < nT; kt++) {
        const int buf = kt & 1;
        if (kt + 1 < nT) G2_LDG((kt + 1) * TK);
        compute_tile(As[buf], Bsd[buf], acc, tx, ty);
        if (kt + 1 < nT) {
            G2_STS(1 - buf);
            __syncthreads();
        }
    }
#undef G2_LDG
#undef G2_STS

    // epilogue: v = alpha_old + STEP*acc; alpha = sign(v)*max(|v|-THRESH, 0)
#pragma unroll
    for (int p = 0; p < 8; p++) {
        float lo[8], hi[8];
#pragma unroll
        for (int j = 0; j < 8; j++) unpack2(acc[p][j], lo[j], hi[j]);
        const int r0 = m0 + ty * 16 + 2 * p;
        const int col = n0 + tx * 8;
#pragma unroll
        for (int h = 0; h < 2; h++) {
            const int row = r0 + h;
            const float* vals = h ? hi : lo;
            float* cptr = alpha + (size_t)row * DICT + col;
#pragma unroll
            for (int j = 0; j < 8; j += 4) {
                float4 oldv;
                if (FIRST) { oldv.x = oldv.y = oldv.z = oldv.w = 0.0f; }
                else       { oldv = *reinterpret_cast<const float4*>(cptr + j); }
                float4 o;
                float v, s;
                v = oldv.x + STEP_SZ * vals[j + 0]; s = fabsf(v) - THRESH; o.x = s > 0.0f ? copysignf(s, v) : 0.0f;
                v = oldv.y + STEP_SZ * vals[j + 1]; s = fabsf(v) - THRESH; o.y = s > 0.0f ? copysignf(s, v) : 0.0f;
                v = oldv.z + STEP_SZ * vals[j + 2]; s = fabsf(v) - THRESH; o.z = s > 0.0f ? copysignf(s, v) : 0.0f;
                v = oldv.w + STEP_SZ * vals[j + 3]; s = fabsf(v) - THRESH; o.w = s > 0.0f ? copysignf(s, v) : 0.0f;
                *reinterpret_cast<float4*>(cptr + j) = o;
            }
        }
    }
}

// ---------------- iter 0: resid = X ----------------
__global__ void copy_resid_kernel(const float* __restrict__ X)
{
    int i = blockIdx.x * blockDim.x + threadIdx.x;
    const int n4 = (B_ROWS * EXP_DIM) / 4;
    if (i < n4) {
        reinterpret_cast<float4*>(g_resid)[i] =
            reinterpret_cast<const float4*>(X)[i];
    }
}

// ---------------- top-k (nibble radix select per row) ----------------
__global__ __launch_bounds__(256)
void topk_kernel(float* __restrict__ alpha)
{
    __shared__ unsigned int keys[DICT];
    __shared__ int hist[16];
    __shared__ int s_bucket;
    __shared__ int s_remk;

    const int tid = threadIdx.x;
    float* a = alpha + (size_t)blockIdx.x * DICT;

    for (int i = tid; i < DICT; i += 256)
        keys[i] = __float_as_uint(fabsf(a[i]));
    __syncthreads();

    unsigned int prefix = 0u, mask = 0u;
    int remk = K_SPARSE;

#pragma unroll
    for (int shift = 28; shift >= 0; shift -= 4) {
        if (tid < 16) hist[tid] = 0;
        __syncthreads();
        for (int i = tid; i < DICT; i += 256) {
            unsigned int k = keys[i];
            if ((k & mask) == prefix)
                atomicAdd(&hist[(k >> shift) & 15], 1);
        }
        __syncthreads();
        if (tid == 0) {
            int r = remk, b = 15;
            for (; b > 0; b--) {
                if (r - hist[b] <= 0) break;
                r -= hist[b];
            }
            s_bucket = b; s_remk = r;
        }
        __syncthreads();
        prefix |= ((unsigned int)s_bucket) << shift;
        mask   |= 0xFu << shift;
        remk = s_remk;
        __syncthreads();
    }

    const unsigned int t = prefix;
    for (int i = tid; i < DICT; i += 256)
        if (keys[i] < t) a[i] = 0.0f;
}

// ---------------- launch ----------------
extern "C" void kernel_launch(void* const* d_in, const int* in_sizes, int n_in,
                              void* d_out, int out_size)
{
    const float* X    = (const float*)d_in[0];   // [8192, 1024]
    const float* Dmat = (const float*)d_in[1];   // [4096, 1024]
    float* alpha      = (float*)d_out;           // [8192, 4096]

    cudaFuncSetAttribute(gemm1_kernel,        cudaFuncAttributeMaxDynamicSharedMemorySize, SMEM_BYTES);
    cudaFuncSetAttribute(gemm2_kernel<false>, cudaFuncAttributeMaxDynamicSharedMemorySize, SMEM_BYTES);
    cudaFuncSetAttribute(gemm2_kernel<true>,  cudaFuncAttributeMaxDynamicSharedMemorySize, SMEM_BYTES);

    const dim3 blk(NTHREADS);
    const dim3 g1(EXP_DIM / TN, B_ROWS / TM);    // ( 8, 32)
    const dim3 g2(DICT    / TN, B_ROWS / TM);    // (32, 32)

    // iter 0: alpha = 0 -> resid = X, then first alpha update
    {
        const int n4 = (B_ROWS * EXP_DIM) / 4;
        copy_resid_kernel<<<(n4 + 255) / 256, 256>>>(X);
        gemm2_kernel<true><<<g2, blk, SMEM_BYTES>>>(Dmat, alpha);
    }
    // iterations 1..19
    for (int it = 1; it < N_ITERS; it++) {
        gemm1_kernel<<<g1, blk, SMEM_BYTES>>>(alpha, Dmat, X);
        gemm2_kernel<false><<<g2, blk, SMEM_BYTES>>>(Dmat, alpha);
    }
    // hard top-k sparsification
    topk_kernel<<<B_ROWS, blk>>>(alpha);
}

// round 14
// speedup vs baseline: 3.1924x; 3.1924x over previous
#include <cuda_runtime.h>
#include <cstdint>
#include <math.h>

// ---------------- problem constants ----------------
#define B_ROWS   8192
#define EXP_DIM  1024
#define DICT     4096
#define N_ITERS  20
#define STEP_SZ  0.1f
#define THRESH   0.01f   // REG * STEP
#define K_SPARSE 409

// ---------------- tiling ----------------
#define TM 256
#define TN 128
#define TK 16
#define ALD 256          // A smem leading dim (floats)
#define BLD 128          // B smem leading dim (floats), unit-permuted rows
#define NTHREADS 256
#define SMEM_BYTES ((2 * TK * ALD + 2 * TK * BLD) * 4)   // 49152

// B row unit permutation: col n (0..127) -> float offset within row.
// unit u = n>>3 ; half = (n>>2)&1 ; offset = half*64 + u*4 + (n&3)
// => thread tx reads float4s at [tx*4] (cols tx*8..+3) and [64+tx*4] (cols tx*8+4..+7):
//    16 consecutive 16B units per instruction -> conflict-free (2-phase floor).

// scratch: residual [8192 x 1024] fp32 (allocation-free device global)
__device__ float g_resid[(size_t)B_ROWS * EXP_DIM];

// ---------------- f32x2 packed helpers (Blackwell FFMA2) ----------------
typedef unsigned long long u64;

__device__ __forceinline__ u64 pack2(float lo, float hi) {
    u64 r;
    asm("mov.b64 %0, {%1, %2};" : "=l"(r) : "f"(lo), "f"(hi));
    return r;
}
__device__ __forceinline__ void unpack2(u64 v, float& lo, float& hi) {
    asm("mov.b64 {%0, %1}, %2;" : "=f"(lo), "=f"(hi) : "l"(v));
}
__device__ __forceinline__ void fma2(u64& d, u64 a, u64 b) {
    asm("fma.rn.f32x2 %0, %1, %2, %0;" : "+l"(d) : "l"(a), "l"(b));
}

// ---------------- compute core: 16 k-steps on one smem buffer ----------------
// Thread tile 16(M) x 8(N). acc[p][j]: rows ty*16 + {2p,2p+1}, col tx*8 + j.
// A fragment: native u64 M-pairs (broadcast LDS). B: conflict-free permuted units.
__device__ __forceinline__ void compute_tile(const float (*As)[ALD],
                                             const float (*Bs)[BLD],
                                             u64 acc[8][8], int tx, int ty)
{
#pragma unroll
    for (int k = 0; k < TK; k++) {
        const ulonglong2* pA = reinterpret_cast<const ulonglong2*>(&As[k][ty * 16]);
        ulonglong2 a0 = pA[0], a1 = pA[1], a2 = pA[2], a3 = pA[3];
        u64 ap[8] = {a0.x, a0.y, a1.x, a1.y, a2.x, a2.y, a3.x, a3.y};

        float4 bv0 = *reinterpret_cast<const float4*>(&Bs[k][tx * 4]);        // cols tx*8..+3
        float4 bv1 = *reinterpret_cast<const float4*>(&Bs[k][64 + tx * 4]);   // cols tx*8+4..+7
        u64 bd[8];
        bd[0] = pack2(bv0.x, bv0.x); bd[1] = pack2(bv0.y, bv0.y);
        bd[2] = pack2(bv0.z, bv0.z); bd[3] = pack2(bv0.w, bv0.w);
        bd[4] = pack2(bv1.x, bv1.x); bd[5] = pack2(bv1.y, bv1.y);
        bd[6] = pack2(bv1.z, bv1.z); bd[7] = pack2(bv1.w, bv1.w);

#pragma unroll
        for (int p = 0; p < 8; p++)
#pragma unroll
            for (int j = 0; j < 8; j++) fma2(acc[p][j], ap[p], bd[j]);
    }
}

// ---------------------------------------------------------------------------
// GEMM1: resid[8192,1024] = X - alpha[8192,4096] @ D[4096,1024]   (NN)
// ---------------------------------------------------------------------------
__global__ __launch_bounds__(NTHREADS, 1)
void gemm1_kernel(const float* __restrict__ alpha,
                  const float* __restrict__ Dmat,
                  const float* __restrict__ X)
{
    extern __shared__ float smem[];
    float (*As)[TK][ALD] = reinterpret_cast<float (*)[TK][ALD]>(smem);
    float (*Bs)[TK][BLD] = reinterpret_cast<float (*)[TK][BLD]>(smem + 2 * TK * ALD);

    const int tid = threadIdx.x;
    const int tx = tid & 15, ty = tid >> 4;
    const int m0 = blockIdx.y * TM, n0 = blockIdx.x * TN;

    const int arow = tid >> 2;      // 0..63  (+r*64) A row
    const int akq  = tid & 3;       // 0..3   A k-quad
    const int bkk  = tid >> 5;      // 0..7   (+r*8) B k row
    const int bnq  = tid & 31;      // 0..31  B n-quad
    // permuted STS offset for the float4 covering cols bnq*4..+3:
    const int bsoff = ((bnq & 1) ? 64 : 0) + (bnq >> 1) * 4;

    u64 acc[8][8];
#pragma unroll
    for (int p = 0; p < 8; p++)
#pragma unroll
        for (int j = 0; j < 8; j++) acc[p][j] = 0ull;

    float4 pa[4], pb[2];

#define G1_LDG(kt) do {                                                           \
    _Pragma("unroll")                                                             \
    for (int r = 0; r < 4; r++)                                                   \
        pa[r] = *reinterpret_cast<const float4*>(                                 \
            alpha + (size_t)(m0 + arow + r * 64) * DICT + (kt) + akq * 4);        \
    _Pragma("unroll")                                                             \
    for (int r = 0; r < 2; r++)                                                   \
        pb[r] = *reinterpret_cast<const float4*>(                                 \
            Dmat + (size_t)((kt) + bkk + r * 8) * EXP_DIM + n0 + bnq * 4);        \
    } while (0)

#define G1_STS(buf) do {                                                          \
    _Pragma("unroll")                                                             \
    for (int r = 0; r < 4; r++) {                                                 \
        int mm = arow + r * 64;                                                   \
        As[buf][akq * 4 + 0][mm] = pa[r].x;                                       \
        As[buf][akq * 4 + 1][mm] = pa[r].y;                                       \
        As[buf][akq * 4 + 2][mm] = pa[r].z;                                       \
        As[buf][akq * 4 + 3][mm] = pa[r].w;                                       \
    }                                                                             \
    _Pragma("unroll")                                                             \
    for (int r = 0; r < 2; r++)                                                   \
        *reinterpret_cast<float4*>(&Bs[buf][bkk + r * 8][bsoff]) = pb[r];         \
    } while (0)

    G1_LDG(0);
    G1_STS(0);
    __syncthreads();

    const int nT = DICT / TK;
    for (int kt = 0; kt < nT; kt++) {
        const int buf = kt & 1;
        if (kt + 1 < nT) G1_LDG((kt + 1) * TK);
        compute_tile(As[buf], Bs[buf], acc, tx, ty);
        if (kt + 1 < nT) {
            G1_STS(1 - buf);
            __syncthreads();
        }
    }
#undef G1_LDG
#undef G1_STS

    // epilogue: resid = X - acc
#pragma unroll
    for (int p = 0; p < 8; p++) {
        float lo[8], hi[8];
#pragma unroll
        for (int j = 0; j < 8; j++) unpack2(acc[p][j], lo[j], hi[j]);
        const int r0 = m0 + ty * 16 + 2 * p;
        const int col = n0 + tx * 8;
#pragma unroll
        for (int h = 0; h < 2; h++) {
            const int row = r0 + h;
            const float* vals = h ? hi : lo;
            const float* xptr = X + (size_t)row * EXP_DIM + col;
            float* optr = &g_resid[(size_t)row * EXP_DIM + col];
#pragma unroll
            for (int j = 0; j < 8; j += 4) {
                float4 xv = *reinterpret_cast<const float4*>(xptr + j);
                float4 o = make_float4(xv.x - vals[j], xv.y - vals[j + 1],
                                       xv.z - vals[j + 2], xv.w - vals[j + 3]);
                *reinterpret_cast<float4*>(optr + j) = o;
            }
        }
    }
}

// ---------------------------------------------------------------------------
// GEMM2: alpha = shrink(alpha + STEP * resid[8192,1024] @ D^T)    (NT)
// ---------------------------------------------------------------------------
template <bool FIRST>
__global__ __launch_bounds__(NTHREADS, 1)
void gemm2_kernel(const float* __restrict__ Dmat,
                  float* __restrict__ alpha)
{
    extern __shared__ float smem[];
    float (*As)[TK][ALD] = reinterpret_cast<float (*)[TK][ALD]>(smem);
    float (*Bs)[TK][BLD] = reinterpret_cast<float (*)[TK][BLD]>(smem + 2 * TK * ALD);

    const int tid = threadIdx.x;
    const int tx = tid & 15, ty = tid >> 4;
    const int m0 = blockIdx.y * TM, n0 = blockIdx.x * TN;

    const int arow = tid >> 2;      // 0..63 (+r*64)
    const int akq  = tid & 3;       // 0..3

    u64 acc[8][8];
#pragma unroll
    for (int p = 0; p < 8; p++)
#pragma unroll
        for (int j = 0; j < 8; j++) acc[p][j] = 0ull;

    float4 pa[4], pb[2];

#define G2_LDG(kt) do {                                                           \
    _Pragma("unroll")                                                             \
    for (int r = 0; r < 4; r++)                                                   \
        pa[r] = *reinterpret_cast<const float4*>(                                 \
            &g_resid[(size_t)(m0 + arow + r * 64) * EXP_DIM + (kt) + akq * 4]);   \
    _Pragma("unroll")                                                             \
    for (int r = 0; r < 2; r++)                                                   \
        pb[r] = *reinterpret_cast<const float4*>(                                 \
            Dmat + (size_t)(n0 + arow + r * 64) * EXP_DIM + (kt) + akq * 4);      \
    } while (0)

// B STS: col nn (fixed), k rows akq*4+0..3; permuted offset of col nn:
// off(nn) = ((nn&4)?64:0) + (nn>>3)*4 + (nn&3)
#define G2_STS(buf) do {                                                          \
    _Pragma("unroll")                                                             \
    for (int r = 0; r < 4; r++) {                                                 \
        int mm = arow + r * 64;                                                   \
        As[buf][akq * 4 + 0][mm] = pa[r].x;                                       \
        As[buf][akq * 4 + 1][mm] = pa[r].y;                                       \
        As[buf][akq * 4 + 2][mm] = pa[r].z;                                       \
        As[buf][akq * 4 + 3][mm] = pa[r].w;                                       \
    }                                                                             \
    _Pragma("unroll")                                                             \
    for (int r = 0; r < 2; r++) {                                                 \
        int nn = arow + r * 64;                                                   \
        if (nn < TN) {                                                            \
            int off = ((nn & 4) ? 64 : 0) + ((nn >> 3) << 2) + (nn & 3);          \
            Bs[buf][akq * 4 + 0][off] = pb[r].x;                                  \
            Bs[buf][akq * 4 + 1][off] = pb[r].y;                                  \
            Bs[buf][akq * 4 + 2][off] = pb[r].z;                                  \
            Bs[buf][akq * 4 + 3][off] = pb[r].w;                                  \
        }                                                                         \
    } } while (0)

    G2_LDG(0);
    G2_STS(0);
    __syncthreads();

    const int nT = EXP_DIM / TK;
    for (int kt = 0; kt < nT; kt++) {
        const int buf = kt & 1;
        if (kt + 1 < nT) G2_LDG((kt + 1) * TK);
        compute_tile(As[buf], Bs[buf], acc, tx, ty);
        if (kt + 1 < nT) {
            G2_STS(1 - buf);
            __syncthreads();
        }
    }
#undef G2_LDG
#undef G2_STS

    // epilogue: v = alpha_old + STEP*acc; alpha = sign(v)*max(|v|-THRESH, 0)
#pragma unroll
    for (int p = 0; p < 8; p++) {
        float lo[8], hi[8];
#pragma unroll
        for (int j = 0; j < 8; j++) unpack2(acc[p][j], lo[j], hi[j]);
        const int r0 = m0 + ty * 16 + 2 * p;
        const int col = n0 + tx * 8;
#pragma unroll
        for (int h = 0; h < 2; h++) {
            const int row = r0 + h;
            const float* vals = h ? hi : lo;
            float* cptr = alpha + (size_t)row * DICT + col;
#pragma unroll
            for (int j = 0; j < 8; j += 4) {
                float4 oldv;
                if (FIRST) { oldv.x = oldv.y = oldv.z = oldv.w = 0.0f; }
                else       { oldv = *reinterpret_cast<const float4*>(cptr + j); }
                float4 o;
                float v, s;
                v = oldv.x + STEP_SZ * vals[j + 0]; s = fabsf(v) - THRESH; o.x = s > 0.0f ? copysignf(s, v) : 0.0f;
                v = oldv.y + STEP_SZ * vals[j + 1]; s = fabsf(v) - THRESH; o.y = s > 0.0f ? copysignf(s, v) : 0.0f;
                v = oldv.z + STEP_SZ * vals[j + 2]; s = fabsf(v) - THRESH; o.z = s > 0.0f ? copysignf(s, v) : 0.0f;
                v = oldv.w + STEP_SZ * vals[j + 3]; s = fabsf(v) - THRESH; o.w = s > 0.0f ? copysignf(s, v) : 0.0f;
                *reinterpret_cast<float4*>(cptr + j) = o;
            }
        }
    }
}

// ---------------- iter 0: resid = X ----------------
__global__ void copy_resid_kernel(const float* __restrict__ X)
{
    int i = blockIdx.x * blockDim.x + threadIdx.x;
    const int n4 = (B_ROWS * EXP_DIM) / 4;
    if (i < n4) {
        reinterpret_cast<float4*>(g_resid)[i] =
            reinterpret_cast<const float4*>(X)[i];
    }
}

// ---------------- top-k (nibble radix select per row) ----------------
__global__ __launch_bounds__(256)
void topk_kernel(float* __restrict__ alpha)
{
    __shared__ unsigned int keys[DICT];
    __shared__ int hist[16];
    __shared__ int s_bucket;
    __shared__ int s_remk;

    const int tid = threadIdx.x;
    float* a = alpha + (size_t)blockIdx.x * DICT;

    for (int i = tid; i < DICT; i += 256)
        keys[i] = __float_as_uint(fabsf(a[i]));
    __syncthreads();

    unsigned int prefix = 0u, mask = 0u;
    int remk = K_SPARSE;

#pragma unroll
    for (int shift = 28; shift >= 0; shift -= 4) {
        if (tid < 16) hist[tid] = 0;
        __syncthreads();
        for (int i = tid; i < DICT; i += 256) {
            unsigned int k = keys[i];
            if ((k & mask) == prefix)
                atomicAdd(&hist[(k >> shift) & 15], 1);
        }
        __syncthreads();
        if (tid == 0) {
            int r = remk, b = 15;
            for (; b > 0; b--) {
                if (r - hist[b] <= 0) break;
                r -= hist[b];
            }
            s_bucket = b; s_remk = r;
        }
        __syncthreads();
        prefix |= ((unsigned int)s_bucket) << shift;
        mask   |= 0xFu << shift;
        remk = s_remk;
        __syncthreads();
    }

    const unsigned int t = prefix;
    for (int i = tid; i < DICT; i += 256)
        if (keys[i] < t) a[i] = 0.0f;
}

// ---------------- launch ----------------
extern "C" void kernel_launch(void* const* d_in, const int* in_sizes, int n_in,
                              void* d_out, int out_size)
{
    const float* X    = (const float*)d_in[0];   // [8192, 1024]
    const float* Dmat = (const float*)d_in[1];   // [4096, 1024]
    float* alpha      = (float*)d_out;           // [8192, 4096]

    cudaFuncSetAttribute(gemm1_kernel,        cudaFuncAttributeMaxDynamicSharedMemorySize, SMEM_BYTES);
    cudaFuncSetAttribute(gemm2_kernel<false>, cudaFuncAttributeMaxDynamicSharedMemorySize, SMEM_BYTES);
    cudaFuncSetAttribute(gemm2_kernel<true>,  cudaFuncAttributeMaxDynamicSharedMemorySize, SMEM_BYTES);

    const dim3 blk(NTHREADS);
    const dim3 g1(EXP_DIM / TN, B_ROWS / TM);    // ( 8, 32)
    const dim3 g2(DICT    / TN, B_ROWS / TM);    // (32, 32)

    // iter 0: alpha = 0 -> resid = X, then first alpha update
    {
        const int n4 = (B_ROWS * EXP_DIM) / 4;
        copy_resid_kernel<<<(n4 + 255) / 256, 256>>>(X);
        gemm2_kernel<true><<<g2, blk, SMEM_BYTES>>>(Dmat, alpha);
    }
    // iterations 1..19
    for (int it = 1; it < N_ITERS; it++) {
        gemm1_kernel<<<g1, blk, SMEM_BYTES>>>(alpha, Dmat, X);
        gemm2_kernel<false><<<g2, blk, SMEM_BYTES>>>(Dmat, alpha);
    }
    // hard top-k sparsification
    topk_kernel<<<B_ROWS, blk>>>(alpha);
}